// round 16
// baseline (speedup 1.0000x reference)
#include <cuda_runtime.h>
#include <math.h>

// Greedy-collapsed beam search, persistent-grid decoder.
// Round-16: R14 baseline (known-good sync: full-syncthreads bar1, counter+flag
// bar2, warp-0 consumer) + ONE change: per-CTA softmax reduce fused into B1's
// register epilogue (own-masked exp/max over r-lanes), standalone partial
// phase replaced by a 14-entry fold.

#define NCTA  148
#define TPB   512
#define VOCAB 16000
#define EDIM  256
#define HDIM  512
#define BATCH 8
#define PAD_ID 0
#define SOS_ID 1
#define EOS_ID 2

typedef unsigned long long ull;

__device__ float    g_h[2][BATCH * HDIM];
__device__ float4   g_part[NCTA][BATCH];          // x=max, y=sumexp, z=argmax bits
__device__ __align__(128) unsigned g_c1[32];
__device__ __align__(128) unsigned g_f1[32];
__device__ __align__(128) unsigned g_c2[32];
__device__ __align__(128) unsigned g_f2[32];
__device__ __align__(128) uint2    g_res[BATCH];  // x=argmax token, y=S bits

// dynamic smem layout (float offsets)
#define SMF_H03   0
#define SMF_H47   2048
#define SMF_HN    4096
#define SMF_LOG   8224                      // 112*9
#define SMF_WIH   9232                      // 7*768
#define SMF_WHH   14608                     // 7*1536
#define SMF_RM    25360                     // 14*9 per-warp max
#define SMF_RI    25486                     // 14*9 per-warp argmax bits
#define SMF_RS    25612                     // 14*9 per-warp sumexp
#define SMF_TOTAL 25738
#define SMEM_BYTES (SMF_TOTAL * 4)

__global__ void decoder_init(const float* __restrict__ hidden) {
    int t = blockIdx.x * blockDim.x + threadIdx.x;
    if (t < BATCH * HDIM) g_h[0][t] = hidden[t];
    if (t == 0) { g_c1[0] = 0; g_f1[0] = 0; g_c2[0] = 0; g_f2[0] = 0; }
}

__device__ __forceinline__ ull fma2(ull a, ull b, ull c) {
    ull d; asm("fma.rn.f32x2 %0, %1, %2, %3;" : "=l"(d) : "l"(a), "l"(b), "l"(c)); return d;
}
__device__ __forceinline__ ull add2(ull a, ull b) {
    ull d; asm("add.rn.f32x2 %0, %1, %2;" : "=l"(d) : "l"(a), "l"(b)); return d;
}
__device__ __forceinline__ ull bcast2(float x) {
    ull d; asm("mov.b64 %0, {%1, %1};" : "=l"(d) : "r"(__float_as_uint(x))); return d;
}
__device__ __forceinline__ void red_release(unsigned* p) {
    asm volatile("red.release.gpu.global.add.u32 [%0], %1;" :: "l"(p), "r"(1u) : "memory");
}
__device__ __forceinline__ unsigned ld_acquire(unsigned* p) {
    unsigned v; asm volatile("ld.global.acquire.gpu.b32 %0, [%1];" : "=r"(v) : "l"(p) : "memory"); return v;
}
__device__ __forceinline__ void st_release(unsigned* p, unsigned v) {
    asm volatile("st.global.release.gpu.b32 [%0], %1;" :: "l"(p), "r"(v) : "memory");
}

__device__ __forceinline__ void stage_h(const float* src, float* smf, int tid) {
    float v[BATCH];
    #pragma unroll
    for (int b = 0; b < BATCH; b++) v[b] = __ldcg(src + b * HDIM + tid);
    ((float4*)(smf + SMF_H03))[tid] = make_float4(v[0], v[1], v[2], v[3]);
    ((float4*)(smf + SMF_H47))[tid] = make_float4(v[4], v[5], v[6], v[7]);
    #pragma unroll
    for (int b = 0; b < BATCH; b++) smf[SMF_HN + b * 516 + tid] = v[b];
}

__device__ __forceinline__ void gru_gh(const float* smf, int wp, int gb, int gg,
                                       float& hrp, float& hzp, float& hnp) {
    const float* hb = smf + SMF_HN + gb * 516;
    const float* wh = smf + SMF_WHH + wp * 1536;
    float r = 0.f, z = 0.f, n = 0.f;
    #pragma unroll 4
    for (int it = 0; it < 16; ++it) {
        const int c = it * 8 + gg;
        float4 h  = *(const float4*)(hb + c * 4);
        float4 ar = *(const float4*)(wh + c * 4);
        float4 az = *(const float4*)(wh + 512 + c * 4);
        float4 an = *(const float4*)(wh + 1024 + c * 4);
        r += h.x*ar.x + h.y*ar.y + h.z*ar.z + h.w*ar.w;
        z += h.x*az.x + h.y*az.y + h.z*az.z + h.w*az.w;
        n += h.x*an.x + h.y*an.y + h.z*an.z + h.w*an.w;
    }
    hrp = r; hzp = z; hnp = n;
}

__global__ void __launch_bounds__(TPB, 1) decoder_main(
    const float* __restrict__ embedding,
    const float* __restrict__ w_ih,
    const float* __restrict__ w_hh,
    const float* __restrict__ b_ih,
    const float* __restrict__ b_hh,
    const float* __restrict__ w_out,
    const float* __restrict__ b_out,
    float* __restrict__ out,
    int lenseq)
{
    extern __shared__ float smf[];
    __shared__ float s_S[BATCH];
    __shared__ int   s_tok[BATCH], s_done[BATCH];

    const int tid  = threadIdx.x;
    const int wp   = tid >> 5;
    const int lane = tid & 31;
    const int cta  = blockIdx.x;
    const int base  = cta * 108 + (cta < 16 ? cta : 16);
    const int nrows = 108 + (cta < 16 ? 1 : 0);

    const int  task   = wp * NCTA + cta;
    const bool gru_on = (wp < 7) && (task < 2 * HDIM);
    const int  gj     = task >> 1;
    const int  gb     = (task & 1) * 4 + (lane >> 3);
    const int  gg     = lane & 7;

    float bi_r = 0.f, bi_z = 0.f, bi_n = 0.f, bh_r = 0.f, bh_z = 0.f, bh_n = 0.f;
    if (gru_on) {
        float* wi = smf + SMF_WIH + wp * 768;
        float* wh = smf + SMF_WHH + wp * 1536;
        #pragma unroll
        for (int g = 0; g < 3; ++g) {
            const float4* si = (const float4*)(w_ih + (size_t)(gj + g * HDIM) * EDIM);
            float4* di = (float4*)(wi + g * 256);
            for (int i = lane; i < 64; i += 32) di[i] = si[i];
            const float4* sh = (const float4*)(w_hh + (size_t)(gj + g * HDIM) * HDIM);
            float4* dh = (float4*)(wh + g * 512);
            for (int i = lane; i < 128; i += 32) dh[i] = sh[i];
        }
        bi_r = b_ih[gj]; bi_z = b_ih[gj + HDIM]; bi_n = b_ih[gj + 2 * HDIM];
        bh_r = b_hh[gj]; bh_z = b_hh[gj + HDIM]; bh_n = b_hh[gj + 2 * HDIM];
    }
    if (tid < BATCH) s_tok[tid] = SOS_ID;
    stage_h(g_h[0], smf, tid);
    __syncthreads();

    float hrp = 0.f, hzp = 0.f, hnp = 0.f;
    if (gru_on) gru_gh(smf, wp, gb, gg, hrp, hzp, hnp);

    unsigned bt = 0;

    for (int step = 0; step < lenseq; ++step) {
        const int nxt = (step & 1) ^ 1;
        bt += NCTA;

        // ===== Phase 1: gi + gates (w0-6)  ||  C(step-1) (w8-15) ============
        if (gru_on) {
            const int tok = s_tok[gb];
            const float* wi = smf + SMF_WIH + wp * 768;
            const float4* e4 = (const float4*)(embedding + (size_t)tok * EDIM);
            float ir = 0.f, iz = 0.f, in_ = 0.f;
            #pragma unroll
            for (int it = 0; it < 8; ++it) {
                const int c = it * 8 + gg;
                float4 e  = e4[c];
                float4 ar = *(const float4*)(wi + c * 4);
                float4 az = *(const float4*)(wi + 256 + c * 4);
                float4 an = *(const float4*)(wi + 512 + c * 4);
                ir  += e.x*ar.x + e.y*ar.y + e.z*ar.z + e.w*ar.w;
                iz  += e.x*az.x + e.y*az.y + e.z*az.z + e.w*az.w;
                in_ += e.x*an.x + e.y*an.y + e.z*an.z + e.w*an.w;
            }
            float hr = hrp, hz = hzp, hn = hnp;
            #pragma unroll
            for (int off = 1; off < 8; off <<= 1) {
                ir  += __shfl_xor_sync(~0u, ir,  off);
                iz  += __shfl_xor_sync(~0u, iz,  off);
                in_ += __shfl_xor_sync(~0u, in_, off);
                hr  += __shfl_xor_sync(~0u, hr,  off);
                hz  += __shfl_xor_sync(~0u, hz,  off);
                hn  += __shfl_xor_sync(~0u, hn,  off);
            }
            if (gg == 0) {
                const float hold = smf[SMF_HN + gb * 516 + gj];
                float hv;
                if (tok == PAD_ID || tok == EOS_ID) {
                    hv = hold;
                } else {
                    const float rg = 1.f / (1.f + expf(-(ir + bi_r + hr + bh_r)));
                    const float zg = 1.f / (1.f + expf(-(iz + bi_z + hz + bh_z)));
                    const float ng = tanhf(in_ + bi_n + rg * (hn + bh_n));
                    hv = (1.f - zg) * ng + zg * hold;
                }
                g_h[nxt][gb * HDIM + gj] = hv;
            }
        } else if (wp >= 8 && step > 0) {
            const int b = wp - 8;
            float* o = out + ((size_t)(step - 1) * BATCH + b) * VOCAB + base;
            if (s_done[b]) {
                for (int r = lane; r < nrows; r += 32)
                    o[r] = (base + r == PAD_ID) ? 1.f : 0.f;
            } else {
                const float S = s_S[b];
                for (int r = lane; r < nrows; r += 32)
                    o[r] = __fdividef(__expf(smf[SMF_LOG + r * 9 + b]), S);
            }
        }

        // ===== bar1: h ready (agent = warp 7 lane 0), R14 protocol ==========
        __syncthreads();
        if (tid == 224) {
            red_release(&g_c1[0]);
            if (cta == 0) { while (ld_acquire(&g_c1[0]) < bt) {} st_release(&g_f1[0], bt); }
            else          { while (ld_acquire(&g_f1[0]) < bt) {} }
        }
        __syncthreads();

        stage_h(g_h[nxt], smf, tid);
        __syncthreads();

        // ===== B1: logits + fused per-warp softmax reduce (w0-13) ===========
        if (wp < 14) {
            const int rb = min(wp * 8, nrows - 8);
            const float* wr = w_out + (size_t)(base + rb) * HDIM;
            ull v[32];
            #pragma unroll
            for (int i = 0; i < 32; i++) v[i] = 0ull;
            #pragma unroll 2
            for (int k = 0; k < 16; k++) {
                const int d = k * 32 + lane;
                const ulonglong2 hA = *(const ulonglong2*)(smf + SMF_H03 + d * 4);
                const ulonglong2 hB = *(const ulonglong2*)(smf + SMF_H47 + d * 4);
                #pragma unroll
                for (int r = 0; r < 8; r++) {
                    const ull wb = bcast2(wr[(size_t)r * HDIM + d]);
                    v[r*4+0] = fma2(wb, hA.x, v[r*4+0]);
                    v[r*4+1] = fma2(wb, hA.y, v[r*4+1]);
                    v[r*4+2] = fma2(wb, hB.x, v[r*4+2]);
                    v[r*4+3] = fma2(wb, hB.y, v[r*4+3]);
                }
            }
            #pragma unroll
            for (int i = 0; i < 16; i++) {
                ull g = (lane & 16) ? v[i] : v[i + 16];
                ull kp = (lane & 16) ? v[i + 16] : v[i];
                v[i] = add2(kp, __shfl_xor_sync(~0u, g, 16));
            }
            #pragma unroll
            for (int i = 0; i < 8; i++) {
                ull g = (lane & 8) ? v[i] : v[i + 8];
                ull kp = (lane & 8) ? v[i + 8] : v[i];
                v[i] = add2(kp, __shfl_xor_sync(~0u, g, 8));
            }
            #pragma unroll
            for (int i = 0; i < 4; i++) {
                ull g = (lane & 4) ? v[i] : v[i + 4];
                ull kp = (lane & 4) ? v[i + 4] : v[i];
                v[i] = add2(kp, __shfl_xor_sync(~0u, g, 4));
            }
            #pragma unroll
            for (int i = 0; i < 2; i++) {
                ull g = (lane & 2) ? v[i] : v[i + 2];
                ull kp = (lane & 2) ? v[i + 2] : v[i];
                v[i] = add2(kp, __shfl_xor_sync(~0u, g, 2));
            }
            {
                ull g = (lane & 1) ? v[0] : v[1];
                ull kp = (lane & 1) ? v[1] : v[0];
                v[0] = add2(kp, __shfl_xor_sync(~0u, g, 1));
            }
            // lane l holds slot l: row = rb + (l>>2), batch pair p = l&3
            const int r   = lane >> 2;
            const int p   = lane & 3;
            const int row = rb + r;
            const bool own = row >= wp * 8;             // mask duplicated clamp rows
            const float bo = b_out[base + row];
            const float2 lv = *(float2*)&v[0];
            const float l0 = lv.x + bo, l1 = lv.y + bo;
            smf[SMF_LOG + row * 9 + 2 * p]     = l0;
            smf[SMF_LOG + row * 9 + 2 * p + 1] = l1;
            float e0 = own ? __expf(l0) : 0.f;
            float e1 = own ? __expf(l1) : 0.f;
            float m0 = own ? l0 : -INFINITY;
            float m1 = own ? l1 : -INFINITY;
            int   i0 = own ? (base + row) : 0x7fffffff;
            int   i1 = i0;
            #pragma unroll
            for (int off = 4; off <= 16; off <<= 1) {   // reduce over r-lanes
                e0 += __shfl_xor_sync(~0u, e0, off);
                e1 += __shfl_xor_sync(~0u, e1, off);
                float om = __shfl_xor_sync(~0u, m0, off);
                int   oi = __shfl_xor_sync(~0u, i0, off);
                if (om > m0 || (om == m0 && oi < i0)) { m0 = om; i0 = oi; }
                om = __shfl_xor_sync(~0u, m1, off);
                oi = __shfl_xor_sync(~0u, i1, off);
                if (om > m1 || (om == m1 && oi < i1)) { m1 = om; i1 = oi; }
            }
            if (lane < 4) {                             // r == 0 lanes, p = lane
                smf[SMF_RM + wp * 9 + 2 * p]     = m0;
                smf[SMF_RM + wp * 9 + 2 * p + 1] = m1;
                smf[SMF_RI + wp * 9 + 2 * p]     = __int_as_float(i0);
                smf[SMF_RI + wp * 9 + 2 * p + 1] = __int_as_float(i1);
                smf[SMF_RS + wp * 9 + 2 * p]     = e0;
                smf[SMF_RS + wp * 9 + 2 * p + 1] = e1;
            }
        }
        __syncthreads();

        // ===== fold 14 warp-results -> per-CTA partial (w0-7) ===============
        if (wp < 8) {
            const int b = wp;
            float m = -INFINITY, s = 0.f; int mi = 0x7fffffff;
            if (lane < 14) {
                m  = smf[SMF_RM + lane * 9 + b];
                mi = __float_as_int(smf[SMF_RI + lane * 9 + b]);
                s  = smf[SMF_RS + lane * 9 + b];
            }
            #pragma unroll
            for (int off = 16; off; off >>= 1) {
                const float om = __shfl_xor_sync(~0u, m, off);
                const int   oi = __shfl_xor_sync(~0u, mi, off);
                s += __shfl_xor_sync(~0u, s, off);
                if (om > m || (om == m && oi < mi)) { m = om; mi = oi; }
            }
            if (lane == 0) g_part[cta][b] = make_float4(m, s, __int_as_float(mi), 0.f);
        }
        __syncthreads();

        // ===== bar2 + centralized reduce (R14 protocol), gh overlapped ======
        if (cta == 0) {
            if (tid == 256) {
                red_release(&g_c2[0]);
                while (ld_acquire(&g_c2[0]) < bt) {}
            }
            if (wp >= 8) {
                asm volatile("bar.sync 1, 256;" ::: "memory");
                const int b = wp - 8;
                float m = -INFINITY, S = 0.f; int mi = 0x7fffffff;
                for (int c = lane; c < NCTA; c += 32) {
                    const float4 pr = __ldcg(&g_part[c][b]);
                    S += pr.y;
                    const int oi = __float_as_int(pr.z);
                    if (pr.x > m || (pr.x == m && oi < mi)) { m = pr.x; mi = oi; }
                }
                #pragma unroll
                for (int off = 16; off; off >>= 1) {
                    const float om = __shfl_xor_sync(~0u, m, off);
                    const int   oi = __shfl_xor_sync(~0u, mi, off);
                    S += __shfl_xor_sync(~0u, S, off);
                    if (om > m || (om == m && oi < mi)) { m = om; mi = oi; }
                }
                if (lane == 0) g_res[b] = make_uint2((unsigned)mi, __float_as_uint(S));
                asm volatile("bar.sync 1, 256;" ::: "memory");
                if (tid == 256) st_release(&g_f2[0], bt);
            }
            if (gru_on) gru_gh(smf, wp, gb, gg, hrp, hzp, hnp);
        } else {
            if (tid == 224) {
                red_release(&g_c2[0]);
                while (ld_acquire(&g_f2[0]) < bt) {}
            }
            if (gru_on) gru_gh(smf, wp, gb, gg, hrp, hzp, hnp);
        }
        __syncthreads();

        // ===== consume: token / done / S =====================================
        if (tid < BATCH) {
            unsigned rx, ry;
            asm volatile("ld.global.cg.v2.u32 {%0,%1}, [%2];"
                         : "=r"(rx), "=r"(ry) : "l"(&g_res[tid]));
            const int old = s_tok[tid];
            const int d = (old == PAD_ID) | (old == EOS_ID);
            s_done[tid] = d;
            s_S[tid]    = __uint_as_float(ry);
            s_tok[tid]  = d ? PAD_ID : (int)rx;
        }
        __syncthreads();
    }

    // ===== final C: write last step's probabilities ==========================
    {
        const int b  = tid >> 6;
        const int r0 = tid & 63;
        float* o = out + ((size_t)(lenseq - 1) * BATCH + b) * VOCAB + base;
        if (s_done[b]) {
            for (int r = r0; r < nrows; r += 64)
                o[r] = (base + r == PAD_ID) ? 1.f : 0.f;
        } else {
            const float S = s_S[b];
            for (int r = r0; r < nrows; r += 64)
                o[r] = __fdividef(__expf(smf[SMF_LOG + r * 9 + b]), S);
        }
    }
}

extern "C" void kernel_launch(void* const* d_in, const int* in_sizes, int n_in,
                              void* d_out, int out_size) {
    const float* hidden    = (const float*)d_in[0];
    const float* embedding = (const float*)d_in[1];
    const float* w_ih      = (const float*)d_in[2];
    const float* w_hh      = (const float*)d_in[3];
    const float* b_ih      = (const float*)d_in[4];
    const float* b_hh      = (const float*)d_in[5];
    const float* w_out     = (const float*)d_in[6];
    const float* b_out     = (const float*)d_in[7];
    float* out = (float*)d_out;
    (void)in_sizes; (void)n_in;

    const int lenseq = out_size / (BATCH * VOCAB);
    if (lenseq <= 0) return;

    cudaFuncSetAttribute(decoder_main, cudaFuncAttributeMaxDynamicSharedMemorySize, SMEM_BYTES);
    decoder_init<<<16, 256>>>(hidden);
    decoder_main<<<NCTA, TPB, SMEM_BYTES>>>(embedding, w_ih, w_hh, b_ih, b_hh,
                                            w_out, b_out, out, lenseq);
}